// round 8
// baseline (speedup 1.0000x reference)
#include <cuda_runtime.h>
#include <cuda_bf16.h>
#include <cstdint>

// ---------------- device scratch (no allocations allowed) ----------------
#define N_NODES 50000
#define D_FEAT  128

__device__ float g_neigh[(size_t)N_NODES * D_FEAT];   // 25.6 MB accumulator
__device__ float g_deg[N_NODES];                      // weighted degree
__device__ float g_stats[256];                        // [0:128) colsum, [128:256) colsumsq
__device__ float g_scale[128];
__device__ float g_shift[128];
// W fragment table: [part(hi/lo)][k16 step 0..15][ntile 0..15][lane 0..31] = uint2
__device__ uint2 g_wfrag[2 * 16 * 16 * 32];

// ---------------- helpers ----------------
__device__ __forceinline__ uint32_t pack_bf16(float a, float b) {
    __nv_bfloat16 ha = __float2bfloat16(a);
    __nv_bfloat16 hb = __float2bfloat16(b);
    return (uint32_t)__bfloat16_as_ushort(ha) |
           ((uint32_t)__bfloat16_as_ushort(hb) << 16);
}
__device__ __forceinline__ void cvt_hilo(float2 v, uint32_t& hi, uint32_t& lo) {
    __nv_bfloat16 h0 = __float2bfloat16(v.x);
    __nv_bfloat16 h1 = __float2bfloat16(v.y);
    float r0 = v.x - __bfloat162float(h0);
    float r1 = v.y - __bfloat162float(h1);
    hi = (uint32_t)__bfloat16_as_ushort(h0) |
         ((uint32_t)__bfloat16_as_ushort(h1) << 16);
    lo = pack_bf16(r0, r1);
}

#define MMA16816(d, a, b0v, b1v)                                             \
    asm volatile(                                                            \
        "mma.sync.aligned.m16n8k16.row.col.f32.bf16.bf16.f32 "               \
        "{%0,%1,%2,%3}, {%4,%5,%6,%7}, {%8,%9}, {%0,%1,%2,%3};"              \
        : "+f"((d)[0]), "+f"((d)[1]), "+f"((d)[2]), "+f"((d)[3])             \
        : "r"((a)[0]), "r"((a)[1]), "r"((a)[2]), "r"((a)[3]),                \
          "r"(b0v), "r"(b1v))

// ---------------- kernel 1: zero accumulators ----------------
__global__ void k_zero(int nn4, int nd4) {
    int i = blockIdx.x * blockDim.x + threadIdx.x;
    float4 z = {0.f, 0.f, 0.f, 0.f};
    if (i < nn4) ((float4*)g_neigh)[i] = z;
    if (i < nd4) ((float4*)g_deg)[i] = z;
    if (i < 64)  ((float4*)g_stats)[i] = z;
}

// ---------------- kernel 2: prep W bf16 hi/lo fragment table ----------------
// Logical Wc[k][o]: k<128 -> W_self[o][k]; k>=128 -> W_neigh[o][k-128].
// B fragment (m16n8k16 col-major): for k16 step ks, ntile nt, lane:
//   n = nt*8 + (lane>>2), k0 = ks*16 + (lane&3)*2
//   reg0 = pack(Wc[k0][n],   Wc[k0+1][n])
//   reg1 = pack(Wc[k0+8][n], Wc[k0+9][n])
__global__ void k_wprep(const float* __restrict__ Wneigh,
                        const float* __restrict__ Wself) {
    int t = blockIdx.x * 256 + threadIdx.x;   // 0..16383
    if (t >= 16384) return;
    int part = t >> 13;           // 0 = hi, 1 = lo
    int ks   = (t >> 9) & 15;
    int nt   = (t >> 5) & 15;
    int lane = t & 31;
    int n  = nt * 8 + (lane >> 2);
    int k0 = ks * 16 + (lane & 3) * 2;
    const float* W = (k0 < 128) ? Wself : Wneigh;
    int kk = k0 & 127;
    float w0 = W[n * 128 + kk];
    float w1 = W[n * 128 + kk + 1];
    float w2 = W[n * 128 + kk + 8];
    float w3 = W[n * 128 + kk + 9];
    uint2 v;
    if (part == 0) {
        v.x = pack_bf16(w0, w1);
        v.y = pack_bf16(w2, w3);
    } else {
        float h0 = __bfloat162float(__float2bfloat16(w0));
        float h1 = __bfloat162float(__float2bfloat16(w1));
        float h2 = __bfloat162float(__float2bfloat16(w2));
        float h3 = __bfloat162float(__float2bfloat16(w3));
        v.x = pack_bf16(w0 - h0, w1 - h1);
        v.y = pack_bf16(w2 - h2, w3 - h3);
    }
    g_wfrag[((part * 16 + ks) * 16 + nt) * 32 + lane] = v;
}

// ---------------- kernel 3: edge scatter (one warp per edge) ----------------
__global__ void k_scatter(const float* __restrict__ feat,
                          const int* __restrict__ src,
                          const int* __restrict__ dst,
                          const float* __restrict__ ew,
                          int E) {
    int e = blockIdx.x * 8 + (threadIdx.x >> 5);
    if (e >= E) return;
    int lane = threadIdx.x & 31;
    int s = __ldg(src + e);
    int d = __ldg(dst + e);
    float w = __ldg(ew + e);
    float4 v = __ldg((const float4*)feat + (size_t)s * 32 + lane);
    v.x *= w; v.y *= w; v.z *= w; v.w *= w;
    float4* outp = (float4*)g_neigh + (size_t)d * 32 + lane;
    asm volatile("red.global.add.v4.f32 [%0], {%1,%2,%3,%4};"
                 :: "l"(outp), "f"(v.x), "f"(v.y), "f"(v.z), "f"(v.w)
                 : "memory");
    if (lane == 0) atomicAdd(g_deg + d, w);
}

// ---------------- kernel 4: mma.sync split-bf16 GEMM + bias + relu --------
// CTA: 256 threads (8 warps: 4 M-groups x 2 N-groups), tile 128x128.
// K = 256 (feat | neigh/deg), staged in 4 chunks of 64 as bf16 hi/lo in smem.
#define XS_STRIDE 36   // u32 per row: 32 pairs + 4 pad (conflict-free)

__global__ void __launch_bounds__(256)
k_gemm_mma(const float* __restrict__ feat,
           const float* __restrict__ b_self,
           const float* __restrict__ bias,
           float* __restrict__ out,
           int N) {
    __shared__ uint32_t Xhi[128 * XS_STRIDE];
    __shared__ uint32_t Xlo[128 * XS_STRIDE];

    int tid  = threadIdx.x;
    int wid  = tid >> 5;
    int lane = tid & 31;
    int wm   = wid & 3;        // M group: rows wm*32..+31
    int wn   = wid >> 2;       // N group: cols wn*64..+63
    int n0   = blockIdx.x * 128;
    int g    = lane >> 2;
    int c    = lane & 3;

    float acc[2][8][4];
#pragma unroll
    for (int mt = 0; mt < 2; ++mt)
#pragma unroll
        for (int nt = 0; nt < 8; ++nt)
#pragma unroll
            for (int q = 0; q < 4; ++q) acc[mt][nt][q] = 0.f;

#pragma unroll
    for (int kc = 0; kc < 4; ++kc) {
        // ---- stage X chunk [128 rows x 32 pairs] as bf16 hi/lo ----
        {
            const float2* srcp = (kc < 2) ? (const float2*)feat
                                          : (const float2*)g_neigh;
            int colbase = (kc & 1) * 32;
            bool isn = (kc >= 2);
#pragma unroll
            for (int it = 0; it < 16; ++it) {
                int idx = tid + it * 256;
                int row = idx >> 5;
                int pc  = idx & 31;
                int gn  = n0 + row;
                float2 v = {0.f, 0.f};
                if (gn < N) {
                    v = srcp[(size_t)gn * 64 + colbase + pc];
                    if (isn) {
                        float inv = 1.0f / (g_deg[gn] + 1e-8f);
                        v.x *= inv; v.y *= inv;
                    }
                }
                uint32_t hi, lo;
                cvt_hilo(v, hi, lo);
                Xhi[row * XS_STRIDE + pc] = hi;
                Xlo[row * XS_STRIDE + pc] = lo;
            }
        }
        __syncthreads();

        // ---- compute: 4 k16 steps over this chunk ----
#pragma unroll
        for (int j = 0; j < 4; ++j) {
            uint32_t ahi[2][4], alo[2][4];
#pragma unroll
            for (int mt = 0; mt < 2; ++mt) {
                int r0 = (wm * 32 + mt * 16 + g) * XS_STRIDE + j * 8;
                ahi[mt][0] = Xhi[r0 + c];
                ahi[mt][1] = Xhi[r0 + 8 * XS_STRIDE + c];
                ahi[mt][2] = Xhi[r0 + c + 4];
                ahi[mt][3] = Xhi[r0 + 8 * XS_STRIDE + c + 4];
                alo[mt][0] = Xlo[r0 + c];
                alo[mt][1] = Xlo[r0 + 8 * XS_STRIDE + c];
                alo[mt][2] = Xlo[r0 + c + 4];
                alo[mt][3] = Xlo[r0 + 8 * XS_STRIDE + c + 4];
            }
            int ks = kc * 4 + j;
#pragma unroll
            for (int nt = 0; nt < 8; ++nt) {
                uint2 bhi = __ldg(&g_wfrag[((0 * 16 + ks) * 16 + wn * 8 + nt) * 32 + lane]);
                uint2 blo = __ldg(&g_wfrag[((1 * 16 + ks) * 16 + wn * 8 + nt) * 32 + lane]);
#pragma unroll
                for (int mt = 0; mt < 2; ++mt) {
                    MMA16816(acc[mt][nt], ahi[mt], bhi.x, bhi.y);
                    MMA16816(acc[mt][nt], ahi[mt], blo.x, blo.y);
                    MMA16816(acc[mt][nt], alo[mt], bhi.x, bhi.y);
                }
            }
        }
        __syncthreads();
    }

    // ---- epilogue: bias + relu, float2 stores (32B-sector aligned) ----
    float2 bsum[8];
#pragma unroll
    for (int nt = 0; nt < 8; ++nt) {
        int p = wn * 32 + nt * 4 + c;       // float2 index into 128-col row
        float2 b1 = __ldg((const float2*)b_self + p);
        float2 b2 = __ldg((const float2*)bias + p);
        bsum[nt].x = b1.x + b2.x;
        bsum[nt].y = b1.y + b2.y;
    }
#pragma unroll
    for (int mt = 0; mt < 2; ++mt) {
        int r0 = n0 + wm * 32 + mt * 16 + g;
        int r1 = r0 + 8;
#pragma unroll
        for (int nt = 0; nt < 8; ++nt) {
            int p = wn * 32 + nt * 4 + c;
            if (r0 < N) {
                float2 v;
                v.x = fmaxf(acc[mt][nt][0] + bsum[nt].x, 0.f);
                v.y = fmaxf(acc[mt][nt][1] + bsum[nt].y, 0.f);
                ((float2*)out)[(size_t)r0 * 64 + p] = v;
            }
            if (r1 < N) {
                float2 v;
                v.x = fmaxf(acc[mt][nt][2] + bsum[nt].x, 0.f);
                v.y = fmaxf(acc[mt][nt][3] + bsum[nt].y, 0.f);
                ((float2*)out)[(size_t)r1 * 64 + p] = v;
            }
        }
    }
}

// ---------------- kernel 5: BN column stats over out ----------------
__global__ void k_stats(const float* __restrict__ out, int N) {
    __shared__ float s1[256], s2[256];
    int tid = threadIdx.x;
    int c = tid & 127;
    int half = tid >> 7;
    int r0 = blockIdx.x * 512 + half;
    int r1 = min(N, blockIdx.x * 512 + 512);
    float s = 0.f, ss = 0.f;
    for (int r = r0; r < r1; r += 2) {
        float v = out[(size_t)r * 128 + c];
        s += v; ss += v * v;
    }
    s1[tid] = s; s2[tid] = ss;
    __syncthreads();
    if (tid < 128) {
        atomicAdd(&g_stats[c], s1[tid] + s1[tid + 128]);
        atomicAdd(&g_stats[128 + c], s2[tid] + s2[tid + 128]);
    }
}

// ---------------- kernel 6: finalize BN scale/shift ----------------
__global__ void k_bnfin(const float* __restrict__ gamma,
                        const float* __restrict__ beta,
                        float invN) {
    int c = threadIdx.x;
    float mu  = g_stats[c] * invN;
    float var = fmaxf(g_stats[128 + c] * invN - mu * mu, 0.f);
    float sc  = __ldg(gamma + c) * rsqrtf(var + 1e-5f);
    g_scale[c] = sc;
    g_shift[c] = __ldg(beta + c) - mu * sc;
}

// ---------------- kernel 7: apply BN elementwise ----------------
__global__ void k_apply(float* __restrict__ out, int n4) {
    int i = blockIdx.x * blockDim.x + threadIdx.x;
    if (i >= n4) return;
    int c = i & 31;
    float4 v  = ((float4*)out)[i];
    float4 sc = ((const float4*)g_scale)[c];
    float4 sh = ((const float4*)g_shift)[c];
    v.x = fmaf(v.x, sc.x, sh.x);
    v.y = fmaf(v.y, sc.y, sh.y);
    v.z = fmaf(v.z, sc.z, sh.z);
    v.w = fmaf(v.w, sc.w, sh.w);
    ((float4*)out)[i] = v;
}

// ---------------- launch ----------------
extern "C" void kernel_launch(void* const* d_in, const int* in_sizes, int n_in,
                              void* d_out, int out_size) {
    const float* feat   = (const float*)d_in[0];
    const int*   src    = (const int*)d_in[1];
    const int*   dst    = (const int*)d_in[2];
    const float* ew     = (const float*)d_in[3];
    const float* Wneigh = (const float*)d_in[4];
    const float* Wself  = (const float*)d_in[5];
    const float* b_self = (const float*)d_in[6];
    const float* bias   = (const float*)d_in[7];
    const float* gamma  = (const float*)d_in[8];
    const float* beta   = (const float*)d_in[9];
    float* out = (float*)d_out;

    int N = in_sizes[0] / 128;
    int E = in_sizes[1];

    int nn4 = N * 32;
    int nd4 = (N + 3) / 4;
    k_zero<<<(nn4 + 255) / 256, 256>>>(nn4, nd4);
    k_wprep<<<64, 256>>>(Wneigh, Wself);
    k_scatter<<<(E + 7) / 8, 256>>>(feat, src, dst, ew, E);
    k_gemm_mma<<<(N + 127) / 128, 256>>>(feat, b_self, bias, out, N);
    k_stats<<<(N + 511) / 512, 256>>>(out, N);
    k_bnfin<<<1, 128>>>(gamma, beta, 1.0f / (float)N);
    k_apply<<<(nn4 + 255) / 256, 256>>>(out, nn4);
}

// round 10
// speedup vs baseline: 1.2881x; 1.2881x over previous
#include <cuda_runtime.h>
#include <cuda_bf16.h>
#include <cstdint>

// ---------------- device scratch (no allocations allowed) ----------------
#define N_NODES 50000
#define E_MAX   800000
#define D_FEAT  128

__device__ float g_neigh[(size_t)N_NODES * D_FEAT];   // aggregated (unnormalized)
__device__ float g_deg[N_NODES];                      // weighted degree
__device__ float g_stats[256];                        // colsum / colsumsq
__device__ float g_scale[128];
__device__ float g_shift[128];
// CSR build
__device__ int   g_cnt[N_NODES];
__device__ int   g_rowptr[N_NODES + 1];
__device__ int   g_fill[N_NODES];
__device__ int   g_esrc[E_MAX];
__device__ float g_ewp[E_MAX];
// W fragment table: [part(hi/lo)][k16 step 0..15][ntile 0..15][lane 0..31] = uint2
__device__ uint2 g_wfrag[2 * 16 * 16 * 32];

// ---------------- helpers ----------------
__device__ __forceinline__ uint32_t pack_bf16(float a, float b) {
    __nv_bfloat16 ha = __float2bfloat16(a);
    __nv_bfloat16 hb = __float2bfloat16(b);
    return (uint32_t)__bfloat16_as_ushort(ha) |
           ((uint32_t)__bfloat16_as_ushort(hb) << 16);
}
__device__ __forceinline__ void cvt_hilo(float2 v, uint32_t& hi, uint32_t& lo) {
    __nv_bfloat16 h0 = __float2bfloat16(v.x);
    __nv_bfloat16 h1 = __float2bfloat16(v.y);
    float r0 = v.x - __bfloat162float(h0);
    float r1 = v.y - __bfloat162float(h1);
    hi = (uint32_t)__bfloat16_as_ushort(h0) |
         ((uint32_t)__bfloat16_as_ushort(h1) << 16);
    lo = pack_bf16(r0, r1);
}

#define MMA16816(d, a, b0v, b1v)                                             \
    asm volatile(                                                            \
        "mma.sync.aligned.m16n8k16.row.col.f32.bf16.bf16.f32 "               \
        "{%0,%1,%2,%3}, {%4,%5,%6,%7}, {%8,%9}, {%0,%1,%2,%3};"              \
        : "+f"((d)[0]), "+f"((d)[1]), "+f"((d)[2]), "+f"((d)[3])             \
        : "r"((a)[0]), "r"((a)[1]), "r"((a)[2]), "r"((a)[3]),                \
          "r"(b0v), "r"(b1v))

// ---------------- kernel 1: zero small state ----------------
__global__ void k_zero(int N) {
    int i = blockIdx.x * blockDim.x + threadIdx.x;
    if (i < N) g_cnt[i] = 0;
    if (i < 256) g_stats[i] = 0.f;
}

// ---------------- kernel 2: prep W bf16 hi/lo fragment table ----------------
__global__ void k_wprep(const float* __restrict__ Wneigh,
                        const float* __restrict__ Wself) {
    int t = blockIdx.x * 256 + threadIdx.x;   // 0..16383
    if (t >= 16384) return;
    int part = t >> 13;
    int ks   = (t >> 9) & 15;
    int nt   = (t >> 5) & 15;
    int lane = t & 31;
    int n  = nt * 8 + (lane >> 2);
    int k0 = ks * 16 + (lane & 3) * 2;
    const float* W = (k0 < 128) ? Wself : Wneigh;
    int kk = k0 & 127;
    float w0 = W[n * 128 + kk];
    float w1 = W[n * 128 + kk + 1];
    float w2 = W[n * 128 + kk + 8];
    float w3 = W[n * 128 + kk + 9];
    uint2 v;
    if (part == 0) {
        v.x = pack_bf16(w0, w1);
        v.y = pack_bf16(w2, w3);
    } else {
        float h0 = __bfloat162float(__float2bfloat16(w0));
        float h1 = __bfloat162float(__float2bfloat16(w1));
        float h2 = __bfloat162float(__float2bfloat16(w2));
        float h3 = __bfloat162float(__float2bfloat16(w3));
        v.x = pack_bf16(w0 - h0, w1 - h1);
        v.y = pack_bf16(w2 - h2, w3 - h3);
    }
    g_wfrag[((part * 16 + ks) * 16 + nt) * 32 + lane] = v;
}

// ---------------- kernel 3a: histogram of dst ----------------
__global__ void k_hist(const int* __restrict__ dst, int E) {
    int e = blockIdx.x * blockDim.x + threadIdx.x;
    if (e < E) atomicAdd(&g_cnt[__ldg(dst + e)], 1);
}

// ---------------- kernel 3b: single-block exclusive scan ----------------
__global__ void k_scan(int N, int E) {
    __shared__ int sp[1024];
    int tid = threadIdx.x;
    int per = (N + 1023) / 1024;
    int base = tid * per;
    int s = 0;
    for (int i = 0; i < per; ++i) {
        int idx = base + i;
        if (idx < N) s += g_cnt[idx];
    }
    sp[tid] = s;
    __syncthreads();
    for (int off = 1; off < 1024; off <<= 1) {
        int v = (tid >= off) ? sp[tid - off] : 0;
        __syncthreads();
        sp[tid] += v;
        __syncthreads();
    }
    int run = sp[tid] - s;   // exclusive prefix of this thread's range
    for (int i = 0; i < per; ++i) {
        int idx = base + i;
        if (idx < N) {
            g_rowptr[idx] = run;
            g_fill[idx] = run;
            run += g_cnt[idx];
        }
    }
    if (tid == 1023) g_rowptr[N] = E;
}

// ---------------- kernel 3c: place edges into buckets ----------------
__global__ void k_place(const int* __restrict__ src,
                        const int* __restrict__ dst,
                        const float* __restrict__ ew,
                        int E) {
    int e = blockIdx.x * blockDim.x + threadIdx.x;
    if (e >= E) return;
    int d = __ldg(dst + e);
    int pos = atomicAdd(&g_fill[d], 1);
    g_esrc[pos] = __ldg(src + e);
    g_ewp[pos] = __ldg(ew + e);
}

// ---------------- kernel 3d: warp-per-node gather aggregation ----------------
__global__ void __launch_bounds__(256)
k_agg(const float* __restrict__ feat, int N) {
    int n = blockIdx.x * 8 + (threadIdx.x >> 5);
    if (n >= N) return;
    int lane = threadIdx.x & 31;
    int b = g_rowptr[n];
    int eend = g_rowptr[n + 1];
    float4 acc = {0.f, 0.f, 0.f, 0.f};
    float ws = 0.f;
    int e = b;
    for (; e + 1 < eend; e += 2) {
        int s0 = g_esrc[e];
        int s1 = g_esrc[e + 1];
        float w0 = g_ewp[e];
        float w1 = g_ewp[e + 1];
        float4 v0 = __ldg((const float4*)feat + (size_t)s0 * 32 + lane);
        float4 v1 = __ldg((const float4*)feat + (size_t)s1 * 32 + lane);
        acc.x += w0 * v0.x + w1 * v1.x;
        acc.y += w0 * v0.y + w1 * v1.y;
        acc.z += w0 * v0.z + w1 * v1.z;
        acc.w += w0 * v0.w + w1 * v1.w;
        ws += w0 + w1;
    }
    if (e < eend) {
        int s0 = g_esrc[e];
        float w0 = g_ewp[e];
        float4 v0 = __ldg((const float4*)feat + (size_t)s0 * 32 + lane);
        acc.x += w0 * v0.x;
        acc.y += w0 * v0.y;
        acc.z += w0 * v0.z;
        acc.w += w0 * v0.w;
        ws += w0;
    }
    ((float4*)g_neigh)[(size_t)n * 32 + lane] = acc;
    if (lane == 0) g_deg[n] = ws;
}

// ---------------- kernel 4: mma.sync split-bf16 GEMM + bias + relu --------
// CTA: 512 threads (16 warps: 8 M-groups x 2 N-groups), tile 128x128.
#define XS_STRIDE 36

__global__ void __launch_bounds__(512)
k_gemm_mma(const float* __restrict__ feat,
           const float* __restrict__ b_self,
           const float* __restrict__ bias,
           float* __restrict__ out,
           int N) {
    __shared__ uint32_t Xhi[128 * XS_STRIDE];
    __shared__ uint32_t Xlo[128 * XS_STRIDE];

    int tid  = threadIdx.x;
    int wid  = tid >> 5;
    int lane = tid & 31;
    int wm   = wid & 7;        // M group: rows wm*16..+15
    int wn   = wid >> 3;       // N group: cols wn*64..+63
    int n0   = blockIdx.x * 128;
    int g    = lane >> 2;
    int c    = lane & 3;

    float acc[8][4];
#pragma unroll
    for (int nt = 0; nt < 8; ++nt)
#pragma unroll
        for (int q = 0; q < 4; ++q) acc[nt][q] = 0.f;

#pragma unroll
    for (int kc = 0; kc < 4; ++kc) {
        // ---- stage X chunk [128 rows x 32 pairs] as bf16 hi/lo ----
        {
            const float2* srcp = (kc < 2) ? (const float2*)feat
                                          : (const float2*)g_neigh;
            int colbase = (kc & 1) * 32;
            bool isn = (kc >= 2);
#pragma unroll
            for (int it = 0; it < 8; ++it) {
                int idx = tid + it * 512;
                int row = idx >> 5;
                int pc  = idx & 31;
                int gn  = n0 + row;
                float2 v = {0.f, 0.f};
                if (gn < N) {
                    v = srcp[(size_t)gn * 64 + colbase + pc];
                    if (isn) {
                        float inv = 1.0f / (g_deg[gn] + 1e-8f);
                        v.x *= inv; v.y *= inv;
                    }
                }
                uint32_t hi, lo;
                cvt_hilo(v, hi, lo);
                Xhi[row * XS_STRIDE + pc] = hi;
                Xlo[row * XS_STRIDE + pc] = lo;
            }
        }
        __syncthreads();

        // ---- compute: 4 k16 steps over this chunk ----
#pragma unroll
        for (int j = 0; j < 4; ++j) {
            uint32_t ahi[4], alo[4];
            {
                int r0 = (wm * 16 + g) * XS_STRIDE + j * 8;
                ahi[0] = Xhi[r0 + c];
                ahi[1] = Xhi[r0 + 8 * XS_STRIDE + c];
                ahi[2] = Xhi[r0 + c + 4];
                ahi[3] = Xhi[r0 + 8 * XS_STRIDE + c + 4];
                alo[0] = Xlo[r0 + c];
                alo[1] = Xlo[r0 + 8 * XS_STRIDE + c];
                alo[2] = Xlo[r0 + c + 4];
                alo[3] = Xlo[r0 + 8 * XS_STRIDE + c + 4];
            }
            int ks = kc * 4 + j;
#pragma unroll
            for (int nt = 0; nt < 8; ++nt) {
                uint2 bhi = __ldg(&g_wfrag[((0 * 16 + ks) * 16 + wn * 8 + nt) * 32 + lane]);
                uint2 blo = __ldg(&g_wfrag[((1 * 16 + ks) * 16 + wn * 8 + nt) * 32 + lane]);
                MMA16816(acc[nt], ahi, bhi.x, bhi.y);
                MMA16816(acc[nt], ahi, blo.x, blo.y);
                MMA16816(acc[nt], alo, bhi.x, bhi.y);
            }
        }
        __syncthreads();
    }

    // ---- epilogue: bias + relu, float2 stores ----
    float2 bsum[8];
#pragma unroll
    for (int nt = 0; nt < 8; ++nt) {
        int p = wn * 32 + nt * 4 + c;
        float2 b1 = __ldg((const float2*)b_self + p);
        float2 b2 = __ldg((const float2*)bias + p);
        bsum[nt].x = b1.x + b2.x;
        bsum[nt].y = b1.y + b2.y;
    }
    int r0 = n0 + wm * 16 + g;
    int r1 = r0 + 8;
#pragma unroll
    for (int nt = 0; nt < 8; ++nt) {
        int p = wn * 32 + nt * 4 + c;
        if (r0 < N) {
            float2 v;
            v.x = fmaxf(acc[nt][0] + bsum[nt].x, 0.f);
            v.y = fmaxf(acc[nt][1] + bsum[nt].y, 0.f);
            ((float2*)out)[(size_t)r0 * 64 + p] = v;
        }
        if (r1 < N) {
            float2 v;
            v.x = fmaxf(acc[nt][2] + bsum[nt].x, 0.f);
            v.y = fmaxf(acc[nt][3] + bsum[nt].y, 0.f);
            ((float2*)out)[(size_t)r1 * 64 + p] = v;
        }
    }
}

// ---------------- kernel 5: BN column stats over out ----------------
__global__ void k_stats(const float* __restrict__ out, int N) {
    __shared__ float s1[256], s2[256];
    int tid = threadIdx.x;
    int c = tid & 127;
    int half = tid >> 7;
    int r0 = blockIdx.x * 512 + half;
    int r1 = min(N, blockIdx.x * 512 + 512);
    float s = 0.f, ss = 0.f;
    for (int r = r0; r < r1; r += 2) {
        float v = out[(size_t)r * 128 + c];
        s += v; ss += v * v;
    }
    s1[tid] = s; s2[tid] = ss;
    __syncthreads();
    if (tid < 128) {
        atomicAdd(&g_stats[c], s1[tid] + s1[tid + 128]);
        atomicAdd(&g_stats[128 + c], s2[tid] + s2[tid + 128]);
    }
}

// ---------------- kernel 6: finalize BN scale/shift ----------------
__global__ void k_bnfin(const float* __restrict__ gamma,
                        const float* __restrict__ beta,
                        float invN) {
    int c = threadIdx.x;
    float mu  = g_stats[c] * invN;
    float var = fmaxf(g_stats[128 + c] * invN - mu * mu, 0.f);
    float sc  = __ldg(gamma + c) * rsqrtf(var + 1e-5f);
    g_scale[c] = sc;
    g_shift[c] = __ldg(beta + c) - mu * sc;
}

// ---------------- kernel 7: apply BN elementwise ----------------
__global__ void k_apply(float* __restrict__ out, int n4) {
    int i = blockIdx.x * blockDim.x + threadIdx.x;
    if (i >= n4) return;
    int c = i & 31;
    float4 v  = ((float4*)out)[i];
    float4 sc = ((const float4*)g_scale)[c];
    float4 sh = ((const float4*)g_shift)[c];
    v.x = fmaf(v.x, sc.x, sh.x);
    v.y = fmaf(v.y, sc.y, sh.y);
    v.z = fmaf(v.z, sc.z, sh.z);
    v.w = fmaf(v.w, sc.w, sh.w);
    ((float4*)out)[i] = v;
}

// ---------------- launch ----------------
extern "C" void kernel_launch(void* const* d_in, const int* in_sizes, int n_in,
                              void* d_out, int out_size) {
    const float* feat   = (const float*)d_in[0];
    const int*   src    = (const int*)d_in[1];
    const int*   dst    = (const int*)d_in[2];
    const float* ew     = (const float*)d_in[3];
    const float* Wneigh = (const float*)d_in[4];
    const float* Wself  = (const float*)d_in[5];
    const float* b_self = (const float*)d_in[6];
    const float* bias   = (const float*)d_in[7];
    const float* gamma  = (const float*)d_in[8];
    const float* beta   = (const float*)d_in[9];
    float* out = (float*)d_out;

    int N = in_sizes[0] / 128;
    int E = in_sizes[1];

    k_zero<<<(N + 255) / 256, 256>>>(N);
    k_wprep<<<64, 256>>>(Wneigh, Wself);
    k_hist<<<(E + 255) / 256, 256>>>(dst, E);
    k_scan<<<1, 1024>>>(N, E);
    k_place<<<(E + 255) / 256, 256>>>(src, dst, ew, E);
    k_agg<<<(N + 7) / 8, 256>>>(feat, N);
    k_gemm_mma<<<(N + 127) / 128, 512>>>(feat, b_self, bias, out, N);
    k_stats<<<(N + 511) / 512, 256>>>(out, N);
    k_bnfin<<<1, 128>>>(gamma, beta, 1.0f / (float)N);
    k_apply<<<(N * 32 + 255) / 256, 256>>>(out, N * 32);
}

// round 13
// speedup vs baseline: 1.8514x; 1.4373x over previous
#include <cuda_runtime.h>
#include <cuda_bf16.h>
#include <cstdint>

// ---------------- device scratch (no allocations allowed) ----------------
#define N_NODES 50000
#define E_MAX   800000
#define D_FEAT  128
#define SCAN_B  256                       // nodes per scan block
#define NSB     ((N_NODES + SCAN_B - 1) / SCAN_B)   // 196

__device__ float g_neigh[(size_t)N_NODES * D_FEAT];   // aggregated (unnormalized)
__device__ float g_deg[N_NODES];                      // weighted degree
__device__ float g_stats[256];                        // colsum / colsumsq
__device__ float g_scale[128];
__device__ float g_shift[128];
// CSR build
__device__ int   g_cnt[N_NODES];
__device__ int   g_rowptr[N_NODES + 1];
__device__ int   g_fill[N_NODES];
__device__ int   g_bsum[NSB];
__device__ int   g_boff[NSB];
__device__ int   g_esrc[E_MAX];
__device__ float g_ewp[E_MAX];
// W fragment table: [part(hi/lo)][k16 step 0..15][ntile 0..15][lane 0..31] = uint2
__device__ uint2 g_wfrag[2 * 16 * 16 * 32];

// ---------------- helpers ----------------
__device__ __forceinline__ uint32_t pack_bf16(float a, float b) {
    __nv_bfloat16 ha = __float2bfloat16(a);
    __nv_bfloat16 hb = __float2bfloat16(b);
    return (uint32_t)__bfloat16_as_ushort(ha) |
           ((uint32_t)__bfloat16_as_ushort(hb) << 16);
}
__device__ __forceinline__ void cvt_hilo(float2 v, uint32_t& hi, uint32_t& lo) {
    __nv_bfloat16 h0 = __float2bfloat16(v.x);
    __nv_bfloat16 h1 = __float2bfloat16(v.y);
    float r0 = v.x - __bfloat162float(h0);
    float r1 = v.y - __bfloat162float(h1);
    hi = (uint32_t)__bfloat16_as_ushort(h0) |
         ((uint32_t)__bfloat16_as_ushort(h1) << 16);
    lo = pack_bf16(r0, r1);
}

#define MMA16816(d, a, b0v, b1v)                                             \
    asm volatile(                                                            \
        "mma.sync.aligned.m16n8k16.row.col.f32.bf16.bf16.f32 "               \
        "{%0,%1,%2,%3}, {%4,%5,%6,%7}, {%8,%9}, {%0,%1,%2,%3};"              \
        : "+f"((d)[0]), "+f"((d)[1]), "+f"((d)[2]), "+f"((d)[3])             \
        : "r"((a)[0]), "r"((a)[1]), "r"((a)[2]), "r"((a)[3]),                \
          "r"(b0v), "r"(b1v))

// ---------------- kernel 1: zero small state ----------------
__global__ void k_zero(int N) {
    int i = blockIdx.x * blockDim.x + threadIdx.x;
    if (i < N) g_cnt[i] = 0;
    if (i < 256) g_stats[i] = 0.f;
}

// ---------------- kernel 2: prep W bf16 hi/lo fragment table ----------------
__global__ void k_wprep(const float* __restrict__ Wneigh,
                        const float* __restrict__ Wself) {
    int t = blockIdx.x * 256 + threadIdx.x;   // 0..16383
    if (t >= 16384) return;
    int part = t >> 13;
    int ks   = (t >> 9) & 15;
    int nt   = (t >> 5) & 15;
    int lane = t & 31;
    int n  = nt * 8 + (lane >> 2);
    int k0 = ks * 16 + (lane & 3) * 2;
    const float* W = (k0 < 128) ? Wself : Wneigh;
    int kk = k0 & 127;
    float w0 = W[n * 128 + kk];
    float w1 = W[n * 128 + kk + 1];
    float w2 = W[n * 128 + kk + 8];
    float w3 = W[n * 128 + kk + 9];
    uint2 v;
    if (part == 0) {
        v.x = pack_bf16(w0, w1);
        v.y = pack_bf16(w2, w3);
    } else {
        float h0 = __bfloat162float(__float2bfloat16(w0));
        float h1 = __bfloat162float(__float2bfloat16(w1));
        float h2 = __bfloat162float(__float2bfloat16(w2));
        float h3 = __bfloat162float(__float2bfloat16(w3));
        v.x = pack_bf16(w0 - h0, w1 - h1);
        v.y = pack_bf16(w2 - h2, w3 - h3);
    }
    g_wfrag[((part * 16 + ks) * 16 + nt) * 32 + lane] = v;
}

// ---------------- kernel 3a: histogram of dst ----------------
__global__ void k_hist(const int* __restrict__ dst, int E) {
    int e = blockIdx.x * blockDim.x + threadIdx.x;
    if (e < E) atomicAdd(&g_cnt[__ldg(dst + e)], 1);
}

// ---------------- kernel 3b-1: per-block sums ----------------
__global__ void k_scan1(int N) {
    __shared__ int sp[SCAN_B];
    int idx = blockIdx.x * SCAN_B + threadIdx.x;
    int v = (idx < N) ? g_cnt[idx] : 0;
    sp[threadIdx.x] = v;
    __syncthreads();
    for (int off = SCAN_B / 2; off > 0; off >>= 1) {
        if (threadIdx.x < off) sp[threadIdx.x] += sp[threadIdx.x + off];
        __syncthreads();
    }
    if (threadIdx.x == 0) g_bsum[blockIdx.x] = sp[0];
}

// ---------------- kernel 3b-2: scan block sums (single small block) --------
__global__ void k_scan2() {
    __shared__ int sp[NSB];
    int tid = threadIdx.x;
    int v = (tid < NSB) ? g_bsum[tid] : 0;
    if (tid < NSB) sp[tid] = v;
    __syncthreads();
    for (int off = 1; off < NSB; off <<= 1) {
        int t = (tid < NSB && tid >= off) ? sp[tid - off] : 0;
        __syncthreads();
        if (tid < NSB) sp[tid] += t;
        __syncthreads();
    }
    if (tid < NSB) g_boff[tid] = sp[tid] - v;   // exclusive
}

// ---------------- kernel 3b-3: in-block exclusive scan + offset ------------
__global__ void k_scan3(int N, int E) {
    __shared__ int sp[SCAN_B];
    int tid = threadIdx.x;
    int idx = blockIdx.x * SCAN_B + tid;
    int v = (idx < N) ? g_cnt[idx] : 0;
    sp[tid] = v;
    __syncthreads();
    for (int off = 1; off < SCAN_B; off <<= 1) {
        int t = (tid >= off) ? sp[tid - off] : 0;
        __syncthreads();
        sp[tid] += t;
        __syncthreads();
    }
    if (idx < N) {
        int r = g_boff[blockIdx.x] + sp[tid] - v;   // exclusive prefix
        g_rowptr[idx] = r;
        g_fill[idx] = r;
    }
    if (blockIdx.x == 0 && tid == 0) g_rowptr[N] = E;
}

// ---------------- kernel 3c: place edges into buckets ----------------
__global__ void k_place(const int* __restrict__ src,
                        const int* __restrict__ dst,
                        const float* __restrict__ ew,
                        int E) {
    int e = blockIdx.x * blockDim.x + threadIdx.x;
    if (e >= E) return;
    int d = __ldg(dst + e);
    int pos = atomicAdd(&g_fill[d], 1);
    g_esrc[pos] = __ldg(src + e);
    g_ewp[pos] = __ldg(ew + e);
}

// ---------------- kernel 3d: warp-per-node gather aggregation ----------------
__global__ void __launch_bounds__(256)
k_agg(const float* __restrict__ feat, int N) {
    int n = blockIdx.x * 8 + (threadIdx.x >> 5);
    if (n >= N) return;
    int lane = threadIdx.x & 31;
    int b = g_rowptr[n];
    int eend = g_rowptr[n + 1];
    float4 acc = {0.f, 0.f, 0.f, 0.f};
    float ws = 0.f;
    int e = b;
    for (; e + 1 < eend; e += 2) {
        int s0 = g_esrc[e];
        int s1 = g_esrc[e + 1];
        float w0 = g_ewp[e];
        float w1 = g_ewp[e + 1];
        float4 v0 = __ldg((const float4*)feat + (size_t)s0 * 32 + lane);
        float4 v1 = __ldg((const float4*)feat + (size_t)s1 * 32 + lane);
        acc.x += w0 * v0.x + w1 * v1.x;
        acc.y += w0 * v0.y + w1 * v1.y;
        acc.z += w0 * v0.z + w1 * v1.z;
        acc.w += w0 * v0.w + w1 * v1.w;
        ws += w0 + w1;
    }
    if (e < eend) {
        int s0 = g_esrc[e];
        float w0 = g_ewp[e];
        float4 v0 = __ldg((const float4*)feat + (size_t)s0 * 32 + lane);
        acc.x += w0 * v0.x;
        acc.y += w0 * v0.y;
        acc.z += w0 * v0.z;
        acc.w += w0 * v0.w;
        ws += w0;
    }
    ((float4*)g_neigh)[(size_t)n * 32 + lane] = acc;
    if (lane == 0) g_deg[n] = ws;
}

// ---------------- kernel 4: mma.sync split-bf16 GEMM + bias + relu --------
// CTA: 512 threads (16 warps: 8 M-groups x 2 N-groups), tile 128x128.
#define XS_STRIDE 36

__global__ void __launch_bounds__(512)
k_gemm_mma(const float* __restrict__ feat,
           const float* __restrict__ b_self,
           const float* __restrict__ bias,
           float* __restrict__ out,
           int N) {
    __shared__ uint32_t Xhi[128 * XS_STRIDE];
    __shared__ uint32_t Xlo[128 * XS_STRIDE];

    int tid  = threadIdx.x;
    int wid  = tid >> 5;
    int lane = tid & 31;
    int wm   = wid & 7;        // M group: rows wm*16..+15
    int wn   = wid >> 3;       // N group: cols wn*64..+63
    int n0   = blockIdx.x * 128;
    int g    = lane >> 2;
    int c    = lane & 3;

    float acc[8][4];
#pragma unroll
    for (int nt = 0; nt < 8; ++nt)
#pragma unroll
        for (int q = 0; q < 4; ++q) acc[nt][q] = 0.f;

#pragma unroll
    for (int kc = 0; kc < 4; ++kc) {
        // ---- stage X chunk [128 rows x 32 pairs] as bf16 hi/lo ----
        {
            const float2* srcp = (kc < 2) ? (const float2*)feat
                                          : (const float2*)g_neigh;
            int colbase = (kc & 1) * 32;
            bool isn = (kc >= 2);
#pragma unroll
            for (int it = 0; it < 8; ++it) {
                int idx = tid + it * 512;
                int row = idx >> 5;
                int pc  = idx & 31;
                int gn  = n0 + row;
                float2 v = {0.f, 0.f};
                if (gn < N) {
                    v = srcp[(size_t)gn * 64 + colbase + pc];
                    if (isn) {
                        float inv = 1.0f / (g_deg[gn] + 1e-8f);
                        v.x *= inv; v.y *= inv;
                    }
                }
                uint32_t hi, lo;
                cvt_hilo(v, hi, lo);
                Xhi[row * XS_STRIDE + pc] = hi;
                Xlo[row * XS_STRIDE + pc] = lo;
            }
        }
        __syncthreads();

        // ---- compute: 4 k16 steps over this chunk ----
#pragma unroll
        for (int j = 0; j < 4; ++j) {
            uint32_t ahi[4], alo[4];
            {
                int r0 = (wm * 16 + g) * XS_STRIDE + j * 8;
                ahi[0] = Xhi[r0 + c];
                ahi[1] = Xhi[r0 + 8 * XS_STRIDE + c];
                ahi[2] = Xhi[r0 + c + 4];
                ahi[3] = Xhi[r0 + 8 * XS_STRIDE + c + 4];
                alo[0] = Xlo[r0 + c];
                alo[1] = Xlo[r0 + 8 * XS_STRIDE + c];
                alo[2] = Xlo[r0 + c + 4];
                alo[3] = Xlo[r0 + 8 * XS_STRIDE + c + 4];
            }
            int ks = kc * 4 + j;
#pragma unroll
            for (int nt = 0; nt < 8; ++nt) {
                uint2 bhi = __ldg(&g_wfrag[((0 * 16 + ks) * 16 + wn * 8 + nt) * 32 + lane]);
                uint2 blo = __ldg(&g_wfrag[((1 * 16 + ks) * 16 + wn * 8 + nt) * 32 + lane]);
                MMA16816(acc[nt], ahi, bhi.x, bhi.y);
                MMA16816(acc[nt], ahi, blo.x, blo.y);
                MMA16816(acc[nt], alo, bhi.x, bhi.y);
            }
        }
        __syncthreads();
    }

    // ---- epilogue: bias + relu, float2 stores ----
    float2 bsum[8];
#pragma unroll
    for (int nt = 0; nt < 8; ++nt) {
        int p = wn * 32 + nt * 4 + c;
        float2 b1 = __ldg((const float2*)b_self + p);
        float2 b2 = __ldg((const float2*)bias + p);
        bsum[nt].x = b1.x + b2.x;
        bsum[nt].y = b1.y + b2.y;
    }
    int r0 = n0 + wm * 16 + g;
    int r1 = r0 + 8;
#pragma unroll
    for (int nt = 0; nt < 8; ++nt) {
        int p = wn * 32 + nt * 4 + c;
        if (r0 < N) {
            float2 v;
            v.x = fmaxf(acc[nt][0] + bsum[nt].x, 0.f);
            v.y = fmaxf(acc[nt][1] + bsum[nt].y, 0.f);
            ((float2*)out)[(size_t)r0 * 64 + p] = v;
        }
        if (r1 < N) {
            float2 v;
            v.x = fmaxf(acc[nt][2] + bsum[nt].x, 0.f);
            v.y = fmaxf(acc[nt][3] + bsum[nt].y, 0.f);
            ((float2*)out)[(size_t)r1 * 64 + p] = v;
        }
    }
}

// ---------------- kernel 5: BN column stats over out ----------------
__global__ void k_stats(const float* __restrict__ out, int N) {
    __shared__ float s1[256], s2[256];
    int tid = threadIdx.x;
    int c = tid & 127;
    int half = tid >> 7;
    int r0 = blockIdx.x * 512 + half;
    int r1 = min(N, blockIdx.x * 512 + 512);
    float s = 0.f, ss = 0.f;
    for (int r = r0; r < r1; r += 2) {
        float v = out[(size_t)r * 128 + c];
        s += v; ss += v * v;
    }
    s1[tid] = s; s2[tid] = ss;
    __syncthreads();
    if (tid < 128) {
        atomicAdd(&g_stats[c], s1[tid] + s1[tid + 128]);
        atomicAdd(&g_stats[128 + c], s2[tid] + s2[tid + 128]);
    }
}

// ---------------- kernel 6: finalize BN scale/shift ----------------
__global__ void k_bnfin(const float* __restrict__ gamma,
                        const float* __restrict__ beta,
                        float invN) {
    int c = threadIdx.x;
    float mu  = g_stats[c] * invN;
    float var = fmaxf(g_stats[128 + c] * invN - mu * mu, 0.f);
    float sc  = __ldg(gamma + c) * rsqrtf(var + 1e-5f);
    g_scale[c] = sc;
    g_shift[c] = __ldg(beta + c) - mu * sc;
}

// ---------------- kernel 7: apply BN elementwise ----------------
__global__ void k_apply(float* __restrict__ out, int n4) {
    int i = blockIdx.x * blockDim.x + threadIdx.x;
    if (i >= n4) return;
    int c = i & 31;
    float4 v  = ((float4*)out)[i];
    float4 sc = ((const float4*)g_scale)[c];
    float4 sh = ((const float4*)g_shift)[c];
    v.x = fmaf(v.x, sc.x, sh.x);
    v.y = fmaf(v.y, sc.y, sh.y);
    v.z = fmaf(v.z, sc.z, sh.z);
    v.w = fmaf(v.w, sc.w, sh.w);
    ((float4*)out)[i] = v;
}

// ---------------- launch ----------------
extern "C" void kernel_launch(void* const* d_in, const int* in_sizes, int n_in,
                              void* d_out, int out_size) {
    const float* feat   = (const float*)d_in[0];
    const int*   src    = (const int*)d_in[1];
    const int*   dst    = (const int*)d_in[2];
    const float* ew     = (const float*)d_in[3];
    const float* Wneigh = (const float*)d_in[4];
    const float* Wself  = (const float*)d_in[5];
    const float* b_self = (const float*)d_in[6];
    const float* bias   = (const float*)d_in[7];
    const float* gamma  = (const float*)d_in[8];
    const float* beta   = (const float*)d_in[9];
    float* out = (float*)d_out;

    int N = in_sizes[0] / 128;
    int E = in_sizes[1];

    k_zero<<<(N + 255) / 256, 256>>>(N);
    k_wprep<<<64, 256>>>(Wneigh, Wself);
    k_hist<<<(E + 255) / 256, 256>>>(dst, E);
    k_scan1<<<NSB, SCAN_B>>>(N);
    k_scan2<<<1, 256>>>();
    k_scan3<<<NSB, SCAN_B>>>(N, E);
    k_place<<<(E + 255) / 256, 256>>>(src, dst, ew, E);
    k_agg<<<(N + 7) / 8, 256>>>(feat, N);
    k_gemm_mma<<<(N + 127) / 128, 512>>>(feat, b_self, bias, out, N);
    k_stats<<<(N + 511) / 512, 256>>>(out, N);
    k_bnfin<<<1, 128>>>(gamma, beta, 1.0f / (float)N);
    k_apply<<<(N * 32 + 255) / 256, 256>>>(out, N * 32);
}

// round 14
// speedup vs baseline: 2.0201x; 1.0911x over previous
#include <cuda_runtime.h>
#include <cuda_bf16.h>
#include <cstdint>

// ---------------- device scratch (no allocations allowed) ----------------
#define N_NODES 50000
#define E_MAX   800000
#define D_FEAT  128
#define SCAN_B  256
#define NSB     ((N_NODES + SCAN_B - 1) / SCAN_B)   // 196

__device__ float g_neigh[(size_t)N_NODES * D_FEAT];   // aggregated (unnormalized)
__device__ float g_deg[N_NODES];                      // 1/(weighted degree + eps)
__device__ float g_stats[256];                        // colsum / colsumsq
// CSR build
__device__ int   g_cnt[N_NODES];
__device__ int   g_rowptr[N_NODES + 1];
__device__ int   g_fill[N_NODES];
__device__ int   g_bsum[NSB];
__device__ int   g_boff[NSB];
__device__ uint2 g_epack[E_MAX];                      // (src, w-bits)
// W fragment table: [part(hi/lo)][k16 0..15][ntile 0..15][lane 0..31] = uint2
__device__ uint2 g_wfrag[2 * 16 * 16 * 32];

// ---------------- helpers ----------------
__device__ __forceinline__ uint32_t pack_bf16(float a, float b) {
    __nv_bfloat16 ha = __float2bfloat16(a);
    __nv_bfloat16 hb = __float2bfloat16(b);
    return (uint32_t)__bfloat16_as_ushort(ha) |
           ((uint32_t)__bfloat16_as_ushort(hb) << 16);
}
__device__ __forceinline__ void cvt_hilo(float2 v, uint32_t& hi, uint32_t& lo) {
    __nv_bfloat16 h0 = __float2bfloat16(v.x);
    __nv_bfloat16 h1 = __float2bfloat16(v.y);
    float r0 = v.x - __bfloat162float(h0);
    float r1 = v.y - __bfloat162float(h1);
    hi = (uint32_t)__bfloat16_as_ushort(h0) |
         ((uint32_t)__bfloat16_as_ushort(h1) << 16);
    lo = pack_bf16(r0, r1);
}

#define MMA16816(d, a, b0v, b1v)                                             \
    asm volatile(                                                            \
        "mma.sync.aligned.m16n8k16.row.col.f32.bf16.bf16.f32 "               \
        "{%0,%1,%2,%3}, {%4,%5,%6,%7}, {%8,%9}, {%0,%1,%2,%3};"              \
        : "+f"((d)[0]), "+f"((d)[1]), "+f"((d)[2]), "+f"((d)[3])             \
        : "r"((a)[0]), "r"((a)[1]), "r"((a)[2]), "r"((a)[3]),                \
          "r"(b0v), "r"(b1v))

// ---------------- kernel 1: init (zero + W fragment prep merged) -----------
__global__ void k_init(const float* __restrict__ Wneigh,
                       const float* __restrict__ Wself, int N) {
    int b = blockIdx.x;
    if (b < NSB) {
        int i = b * 256 + threadIdx.x;
        if (i < N) g_cnt[i] = 0;
        if (i < 256) g_stats[i] = 0.f;
        return;
    }
    int t = (b - NSB) * 256 + threadIdx.x;   // 0..16383
    if (t >= 16384) return;
    int part = t >> 13;
    int ks   = (t >> 9) & 15;
    int nt   = (t >> 5) & 15;
    int lane = t & 31;
    int n  = nt * 8 + (lane >> 2);
    int k0 = ks * 16 + (lane & 3) * 2;
    const float* W = (k0 < 128) ? Wself : Wneigh;
    int kk = k0 & 127;
    float w0 = W[n * 128 + kk];
    float w1 = W[n * 128 + kk + 1];
    float w2 = W[n * 128 + kk + 8];
    float w3 = W[n * 128 + kk + 9];
    uint2 v;
    if (part == 0) {
        v.x = pack_bf16(w0, w1);
        v.y = pack_bf16(w2, w3);
    } else {
        float h0 = __bfloat162float(__float2bfloat16(w0));
        float h1 = __bfloat162float(__float2bfloat16(w1));
        float h2 = __bfloat162float(__float2bfloat16(w2));
        float h3 = __bfloat162float(__float2bfloat16(w3));
        v.x = pack_bf16(w0 - h0, w1 - h1);
        v.y = pack_bf16(w2 - h2, w3 - h3);
    }
    g_wfrag[((part * 16 + ks) * 16 + nt) * 32 + lane] = v;
}

// ---------------- kernel 2: histogram of dst ----------------
__global__ void k_hist(const int* __restrict__ dst, int E) {
    int e = blockIdx.x * blockDim.x + threadIdx.x;
    if (e < E) atomicAdd(&g_cnt[__ldg(dst + e)], 1);
}

// ---------------- kernel 3: 3-phase scan ----------------
__global__ void k_scan1(int N) {
    __shared__ int sp[SCAN_B];
    int idx = blockIdx.x * SCAN_B + threadIdx.x;
    int v = (idx < N) ? g_cnt[idx] : 0;
    sp[threadIdx.x] = v;
    __syncthreads();
    for (int off = SCAN_B / 2; off > 0; off >>= 1) {
        if (threadIdx.x < off) sp[threadIdx.x] += sp[threadIdx.x + off];
        __syncthreads();
    }
    if (threadIdx.x == 0) g_bsum[blockIdx.x] = sp[0];
}
__global__ void k_scan2() {
    __shared__ int sp[NSB];
    int tid = threadIdx.x;
    int v = (tid < NSB) ? g_bsum[tid] : 0;
    if (tid < NSB) sp[tid] = v;
    __syncthreads();
    for (int off = 1; off < NSB; off <<= 1) {
        int t = (tid < NSB && tid >= off) ? sp[tid - off] : 0;
        __syncthreads();
        if (tid < NSB) sp[tid] += t;
        __syncthreads();
    }
    if (tid < NSB) g_boff[tid] = sp[tid] - v;
}
__global__ void k_scan3(int N, int E) {
    __shared__ int sp[SCAN_B];
    int tid = threadIdx.x;
    int idx = blockIdx.x * SCAN_B + tid;
    int v = (idx < N) ? g_cnt[idx] : 0;
    sp[tid] = v;
    __syncthreads();
    for (int off = 1; off < SCAN_B; off <<= 1) {
        int t = (tid >= off) ? sp[tid - off] : 0;
        __syncthreads();
        sp[tid] += t;
        __syncthreads();
    }
    if (idx < N) {
        int r = g_boff[blockIdx.x] + sp[tid] - v;
        g_rowptr[idx] = r;
        g_fill[idx] = r;
    }
    if (blockIdx.x == 0 && tid == 0) g_rowptr[N] = E;
}

// ---------------- kernel 4: place edges (packed uint2) ----------------
__global__ void k_place(const int* __restrict__ src,
                        const int* __restrict__ dst,
                        const float* __restrict__ ew,
                        int E) {
    int e = blockIdx.x * blockDim.x + threadIdx.x;
    if (e >= E) return;
    int d = __ldg(dst + e);
    int pos = atomicAdd(&g_fill[d], 1);
    g_epack[pos] = make_uint2((uint32_t)__ldg(src + e),
                              __float_as_uint(__ldg(ew + e)));
}

// ---------------- kernel 5: warp-per-node gather aggregation ----------------
__global__ void __launch_bounds__(256)
k_agg(const float* __restrict__ feat, int N) {
    int n = blockIdx.x * 8 + (threadIdx.x >> 5);
    if (n >= N) return;
    int lane = threadIdx.x & 31;
    int b = g_rowptr[n];
    int eend = g_rowptr[n + 1];
    float4 acc = {0.f, 0.f, 0.f, 0.f};
    float ws = 0.f;
    int e = b;
    for (; e + 1 < eend; e += 2) {
        uint2 p0 = g_epack[e];
        uint2 p1 = g_epack[e + 1];
        float w0 = __uint_as_float(p0.y);
        float w1 = __uint_as_float(p1.y);
        float4 v0 = __ldg((const float4*)feat + (size_t)p0.x * 32 + lane);
        float4 v1 = __ldg((const float4*)feat + (size_t)p1.x * 32 + lane);
        acc.x += w0 * v0.x + w1 * v1.x;
        acc.y += w0 * v0.y + w1 * v1.y;
        acc.z += w0 * v0.z + w1 * v1.z;
        acc.w += w0 * v0.w + w1 * v1.w;
        ws += w0 + w1;
    }
    if (e < eend) {
        uint2 p0 = g_epack[e];
        float w0 = __uint_as_float(p0.y);
        float4 v0 = __ldg((const float4*)feat + (size_t)p0.x * 32 + lane);
        acc.x += w0 * v0.x;
        acc.y += w0 * v0.y;
        acc.z += w0 * v0.z;
        acc.w += w0 * v0.w;
        ws += w0;
    }
    ((float4*)g_neigh)[(size_t)n * 32 + lane] = acc;
    if (lane == 0) g_deg[n] = 1.0f / (ws + 1e-8f);   // store reciprocal
}

// ---------------- kernel 6: pipelined mma.sync split-bf16 GEMM -------------
// 512 threads (16 warps: 8 M x 2 N), tile 128x128, K=256 in 4 chunks of 64.
// Double-buffered smem + register prefetch of next chunk.
#define XS_STRIDE 36
#define XBUF_U32  (128 * XS_STRIDE)          // 4608 u32 per (hi|lo) plane
#define GEMM_SMEM (2 * 2 * XBUF_U32 * 4)     // 73728 bytes

__global__ void __launch_bounds__(512)
k_gemm_mma(const float* __restrict__ feat,
           const float* __restrict__ b_self,
           const float* __restrict__ bias,
           float* __restrict__ out,
           int N) {
    extern __shared__ uint32_t sx[];
    int tid  = threadIdx.x;
    int wid  = tid >> 5;
    int lane = tid & 31;
    int wm   = wid & 7;
    int wn   = wid >> 3;
    int n0   = blockIdx.x * 128;
    int g    = lane >> 2;
    int c    = lane & 3;

    float acc[8][4];
#pragma unroll
    for (int nt = 0; nt < 8; ++nt)
#pragma unroll
        for (int q = 0; q < 4; ++q) acc[nt][q] = 0.f;

    float2 pv[8];

    auto stage_load = [&](int kc) {
        const float2* srcp = (kc < 2) ? (const float2*)feat
                                      : (const float2*)g_neigh;
        int colbase = (kc & 1) * 32;
#pragma unroll
        for (int it = 0; it < 8; ++it) {
            int idx = tid + it * 512;
            int row = idx >> 5, pc = idx & 31;
            int gn = n0 + row;
            pv[it] = (gn < N) ? srcp[(size_t)gn * 64 + colbase + pc]
                              : make_float2(0.f, 0.f);
        }
    };
    auto stage_store = [&](int kc, uint32_t* bh, uint32_t* bl) {
        bool isn = (kc >= 2);
#pragma unroll
        for (int it = 0; it < 8; ++it) {
            int idx = tid + it * 512;
            int row = idx >> 5, pc = idx & 31;
            int gn = n0 + row;
            float2 v = pv[it];
            if (isn) {
                float inv = (gn < N) ? g_deg[gn] : 0.f;
                v.x *= inv; v.y *= inv;
            }
            uint32_t hi, lo;
            cvt_hilo(v, hi, lo);
            bh[row * XS_STRIDE + pc] = hi;
            bl[row * XS_STRIDE + pc] = lo;
        }
    };
    auto compute = [&](int kc, const uint32_t* bh, const uint32_t* bl) {
#pragma unroll
        for (int j = 0; j < 4; ++j) {
            uint32_t ahi[4], alo[4];
            int r0 = (wm * 16 + g) * XS_STRIDE + j * 8;
            ahi[0] = bh[r0 + c];
            ahi[1] = bh[r0 + 8 * XS_STRIDE + c];
            ahi[2] = bh[r0 + c + 4];
            ahi[3] = bh[r0 + 8 * XS_STRIDE + c + 4];
            alo[0] = bl[r0 + c];
            alo[1] = bl[r0 + 8 * XS_STRIDE + c];
            alo[2] = bl[r0 + c + 4];
            alo[3] = bl[r0 + 8 * XS_STRIDE + c + 4];
            int ks = kc * 4 + j;
#pragma unroll
            for (int nt = 0; nt < 8; ++nt) {
                uint2 bhi = __ldg(&g_wfrag[((0 * 16 + ks) * 16 + wn * 8 + nt) * 32 + lane]);
                uint2 blo = __ldg(&g_wfrag[((1 * 16 + ks) * 16 + wn * 8 + nt) * 32 + lane]);
                MMA16816(acc[nt], ahi, bhi.x, bhi.y);
                MMA16816(acc[nt], ahi, blo.x, blo.y);
                MMA16816(acc[nt], alo, bhi.x, bhi.y);
            }
        }
    };

    uint32_t* buf0 = sx;
    uint32_t* buf1 = sx + 2 * XBUF_U32;

    // prologue: stage chunk 0
    stage_load(0);
    stage_store(0, buf0, buf0 + XBUF_U32);
    __syncthreads();

#pragma unroll
    for (int kc = 0; kc < 4; ++kc) {
        uint32_t* cb = (kc & 1) ? buf1 : buf0;
        uint32_t* nb = (kc & 1) ? buf0 : buf1;
        if (kc < 3) stage_load(kc + 1);         // global loads overlap MMAs
        compute(kc, cb, cb + XBUF_U32);
        if (kc < 3) {
            stage_store(kc + 1, nb, nb + XBUF_U32);
            __syncthreads();
        }
    }

    // ---- epilogue: bias + relu, float2 stores ----
    float2 bsum[8];
#pragma unroll
    for (int nt = 0; nt < 8; ++nt) {
        int p = wn * 32 + nt * 4 + c;
        float2 b1 = __ldg((const float2*)b_self + p);
        float2 b2 = __ldg((const float2*)bias + p);
        bsum[nt].x = b1.x + b2.x;
        bsum[nt].y = b1.y + b2.y;
    }
    int r0 = n0 + wm * 16 + g;
    int r1 = r0 + 8;
#pragma unroll
    for (int nt = 0; nt < 8; ++nt) {
        int p = wn * 32 + nt * 4 + c;
        if (r0 < N) {
            float2 v;
            v.x = fmaxf(acc[nt][0] + bsum[nt].x, 0.f);
            v.y = fmaxf(acc[nt][1] + bsum[nt].y, 0.f);
            ((float2*)out)[(size_t)r0 * 64 + p] = v;
        }
        if (r1 < N) {
            float2 v;
            v.x = fmaxf(acc[nt][2] + bsum[nt].x, 0.f);
            v.y = fmaxf(acc[nt][3] + bsum[nt].y, 0.f);
            ((float2*)out)[(size_t)r1 * 64 + p] = v;
        }
    }
}

// ---------------- kernel 7: BN column stats over out ----------------
__global__ void k_stats(const float* __restrict__ out, int N) {
    __shared__ float s1[256], s2[256];
    int tid = threadIdx.x;
    int c = tid & 127;
    int half = tid >> 7;
    int r0 = blockIdx.x * 512 + half;
    int r1 = min(N, blockIdx.x * 512 + 512);
    float s = 0.f, ss = 0.f;
    for (int r = r0; r < r1; r += 2) {
        float v = out[(size_t)r * 128 + c];
        s += v; ss += v * v;
    }
    s1[tid] = s; s2[tid] = ss;
    __syncthreads();
    if (tid < 128) {
        atomicAdd(&g_stats[c], s1[tid] + s1[tid + 128]);
        atomicAdd(&g_stats[128 + c], s2[tid] + s2[tid + 128]);
    }
}

// ---------------- kernel 8: apply BN (scale/shift computed in-block) -------
__global__ void k_apply(float* __restrict__ out, int n4,
                        const float* __restrict__ gamma,
                        const float* __restrict__ beta,
                        float invN) {
    __shared__ float4 ssc[32], ssh[32];
    int tid = threadIdx.x;
    if (tid < 32) {
        float4 sc, sh;
        float* scp = (float*)&sc;
        float* shp = (float*)&sh;
#pragma unroll
        for (int q = 0; q < 4; ++q) {
            int col = tid * 4 + q;
            float mu  = g_stats[col] * invN;
            float var = fmaxf(g_stats[128 + col] * invN - mu * mu, 0.f);
            float s   = __ldg(gamma + col) * rsqrtf(var + 1e-5f);
            scp[q] = s;
            shp[q] = __ldg(beta + col) - mu * s;
        }
        ssc[tid] = sc;
        ssh[tid] = sh;
    }
    __syncthreads();
    int i = blockIdx.x * blockDim.x + tid;
    if (i >= n4) return;
    int c = i & 31;
    float4 v  = ((float4*)out)[i];
    float4 sc = ssc[c];
    float4 sh = ssh[c];
    v.x = fmaf(v.x, sc.x, sh.x);
    v.y = fmaf(v.y, sc.y, sh.y);
    v.z = fmaf(v.z, sc.z, sh.z);
    v.w = fmaf(v.w, sc.w, sh.w);
    ((float4*)out)[i] = v;
}

// ---------------- launch ----------------
extern "C" void kernel_launch(void* const* d_in, const int* in_sizes, int n_in,
                              void* d_out, int out_size) {
    const float* feat   = (const float*)d_in[0];
    const int*   src    = (const int*)d_in[1];
    const int*   dst    = (const int*)d_in[2];
    const float* ew     = (const float*)d_in[3];
    const float* Wneigh = (const float*)d_in[4];
    const float* Wself  = (const float*)d_in[5];
    const float* b_self = (const float*)d_in[6];
    const float* bias   = (const float*)d_in[7];
    const float* gamma  = (const float*)d_in[8];
    const float* beta   = (const float*)d_in[9];
    float* out = (float*)d_out;

    int N = in_sizes[0] / 128;
    int E = in_sizes[1];

    cudaFuncSetAttribute(k_gemm_mma, cudaFuncAttributeMaxDynamicSharedMemorySize,
                         GEMM_SMEM);

    k_init<<<NSB + 64, 256>>>(Wneigh, Wself, N);
    k_hist<<<(E + 255) / 256, 256>>>(dst, E);
    k_scan1<<<NSB, SCAN_B>>>(N);
    k_scan2<<<1, 256>>>();
    k_scan3<<<NSB, SCAN_B>>>(N, E);
    k_place<<<(E + 255) / 256, 256>>>(src, dst, ew, E);
    k_agg<<<(N + 7) / 8, 256>>>(feat, N);
    k_gemm_mma<<<(N + 127) / 128, 512, GEMM_SMEM>>>(feat, b_self, bias, out, N);
    k_stats<<<(N + 511) / 512, 256>>>(out, N);
    k_apply<<<(N * 32 + 255) / 256, 256>>>(out, N * 32, gamma, beta,
                                           1.0f / (float)N);
}